// round 11
// baseline (speedup 1.0000x reference)
#include <cuda_runtime.h>
#include <cuda_bf16.h>
#include <math.h>

#define BS 16
#define HDIM 2048
#define QL 768
#define KVL 512
#define DR 64
#define DN 128
#define NH 16
#define NIH 8
#define IDXD 128
#define BLKSZ 128
#define BPS 32
#define MAXKV 4096
#define TOPK 1024
#define NSPLIT 16
#define SPLITROWS 64

#define NZ1 32          /* stage1 K-slices of 64 */
#define NZ2 12          /* stage2 K-slices of 64 */
#define T1DIM 1472
#define T2DIM 4104

#define ATT_SCALE 0.07216878364870323f
#define IDX_SCALE 0.08838834764831845f

#define NBMAX 448
#define SMSZ 57344

// ---------------- scratch ----------------
__device__ float g_t1p[NZ1][BS][T1DIM];
__device__ float g_cq[BS][QL];
__device__ float g_ckv[BS][KVL];
__device__ float g_kr[BS][DR];
__device__ float g_ki[BS][IDXD];
__device__ float g_q[BS][NH * 192];
__device__ float g_qi[BS][NIH * IDXD];
__device__ float g_hw[BS][NIH];
__device__ float g_qpe[BS][NH][DR];
__device__ float g_qlat[BS][NH][KVL];
__device__ float g_isc[BS][MAXKV];
__device__ int   g_sel[BS][TOPK];
__device__ float g_selval[BS][TOPK];
__device__ float g_m[BS][NSPLIT][NH];
__device__ float g_l[BS][NSPLIT][NH];
__device__ float g_op[BS][NSPLIT][NH][KVL];

__device__ unsigned g_barcnt[8];
__device__ unsigned g_ack;

__device__ __forceinline__ void gsync(int id, int nb) {
    __syncthreads();
    if (threadIdx.x == 0) {
        __threadfence();
        atomicAdd(&g_barcnt[id], 1u);
        while (*(volatile unsigned*)&g_barcnt[id] < (unsigned)nb) { __nanosleep(64); }
    }
    __syncthreads();
}

__device__ __forceinline__ float blockSum256(float v, float* buf) {
    int tid = threadIdx.x;
    buf[tid] = v;
    __syncthreads();
    for (int s = 128; s > 0; s >>= 1) {
        if (tid < s) buf[tid] += buf[tid + s];
        __syncthreads();
    }
    float r = buf[0];
    __syncthreads();
    return r;
}

__global__ void __launch_bounds__(256, 3)
k_mega(const float* __restrict__ x, const float* __restrict__ w_dq,
       const float* __restrict__ w_uq_qr, const float* __restrict__ w_uk,
       const float* __restrict__ w_dkv, const float* __restrict__ gamma_cq,
       const float* __restrict__ gamma_ckv, const float* __restrict__ sinp,
       const float* __restrict__ cosp, const int* __restrict__ cidx,
       const float* __restrict__ kvc, const float* __restrict__ krc,
       const int* __restrict__ bt, const int* __restrict__ act_seqs,
       const float* __restrict__ w_idx_qb, const float* __restrict__ w_idxk,
       const float* __restrict__ w_idx_proj, const float* __restrict__ in_g,
       const float* __restrict__ in_b, const float* __restrict__ ikc,
       float* __restrict__ out, int nb)
{
    extern __shared__ __align__(16) char sm_raw[];
    int tid = threadIdx.x;
    int bx = blockIdx.x;

    // ===== P0: stage1 partials, transposed smem [k][b] (384 units) + zero stage2 accumulators =====
    {
        float* s_x = (float*)sm_raw;   // [64][8]
        for (int u = bx; u < 6 * 2 * NZ1; u += nb) {
            int cx = u % 6, bg = (u / 6) & 1, z = u / 12;
            int i0 = z * 64, b0 = bg * 8;
            for (int idx = tid; idx < 512; idx += 256) {
                int i = idx >> 3, b = idx & 7;
                s_x[idx] = x[(b0 + b) * HDIM + i0 + i];
            }
            __syncthreads();
            int col = cx * 256 + tid;
            if (col < T1DIM) {
                const float* W; int stride, c;
                if (col < QL)                 { W = w_dq;   stride = QL;       c = col; }
                else if (col < QL + KVL + DR) { W = w_dkv;  stride = KVL + DR; c = col - QL; }
                else                          { W = w_idxk; stride = IDXD;     c = col - (QL + KVL + DR); }
                const float* wp = W + (size_t)i0 * stride + c;
                float acc[8];
                #pragma unroll
                for (int b = 0; b < 8; b++) acc[b] = 0.f;
                #pragma unroll 8
                for (int i = 0; i < 64; i++) {
                    float w = wp[(size_t)i * stride];
                    float4 xa = *(const float4*)&s_x[i * 8 + 0];
                    float4 xb = *(const float4*)&s_x[i * 8 + 4];
                    acc[0] += xa.x * w; acc[1] += xa.y * w; acc[2] += xa.z * w; acc[3] += xa.w * w;
                    acc[4] += xb.x * w; acc[5] += xb.y * w; acc[6] += xb.z * w; acc[7] += xb.w * w;
                }
                #pragma unroll
                for (int b = 0; b < 8; b++) g_t1p[z][b0 + b][col] = acc[b];
            }
            __syncthreads();
        }
        // zero g_q / g_qi / g_hw (stage2 accumulates into them atomically)
        {
            float* q0 = &g_q[0][0];
            for (int i = bx * 256 + tid; i < BS * NH * 192; i += nb * 256) q0[i] = 0.f;
            float* q1 = &g_qi[0][0];
            for (int i = bx * 256 + tid; i < BS * NIH * IDXD; i += nb * 256) q1[i] = 0.f;
            float* q2 = &g_hw[0][0];
            for (int i = bx * 256 + tid; i < BS * NIH; i += nb * 256) q2[i] = 0.f;
        }
    }
    gsync(0, nb);

    // ===== P1: norms + rope(kr) =====
    {
        float* s_t  = (float*)sm_raw;
        float* sred = (float*)(sm_raw + T1DIM * 4 + 64);
        for (int u = bx; u < BS; u += nb) {
            int b = u;
            for (int i = tid; i < T1DIM; i += 256) {
                float a = 0.f;
                #pragma unroll
                for (int z = 0; z < NZ1; z++) a += g_t1p[z][b][i];
                s_t[i] = a;
            }
            __syncthreads();
            float ss = 0.f;
            for (int i = tid; i < QL; i += 256) ss += s_t[i] * s_t[i];
            ss = blockSum256(ss, sred);
            float r = rsqrtf(ss / (float)QL + 1e-6f);
            for (int i = tid; i < QL; i += 256) g_cq[b][i] = s_t[i] * r * gamma_cq[i];
            float s2 = 0.f;
            for (int i = tid; i < KVL; i += 256) { float v = s_t[QL + i]; s2 += v * v; }
            s2 = blockSum256(s2, sred);
            float r2 = rsqrtf(s2 / (float)KVL + 1e-6f);
            for (int i = tid; i < KVL; i += 256) g_ckv[b][i] = s_t[QL + i] * r2 * gamma_ckv[i];
            if (tid < DR) {
                int d = tid;
                float v = s_t[QL + KVL + d];
                float rot = (d < 32) ? -s_t[QL + KVL + d + 32] : s_t[QL + KVL + d - 32];
                g_kr[b][d] = v * cosp[b * DR + d] + rot * sinp[b * DR + d];
            }
            float sm = 0.f;
            for (int i = tid; i < IDXD; i += 256) sm += s_t[QL + KVL + DR + i];
            sm = blockSum256(sm, sred);
            float mean = sm / (float)IDXD;
            float sv = 0.f;
            for (int i = tid; i < IDXD; i += 256) { float c = s_t[QL + KVL + DR + i] - mean; sv += c * c; }
            sv = blockSum256(sv, sred);
            float rv = rsqrtf(sv / (float)IDXD + 1e-6f);
            for (int i = tid; i < IDXD; i += 256) {
                float c = s_t[QL + KVL + DR + i] - mean;
                g_ki[b][i] = c * rv * in_g[i] + in_b[i];
            }
            __syncthreads();
        }
    }
    gsync(1, nb);

    // ===== P2: stage2, atomicAdd directly into g_q/g_qi/g_hw (408 units) =====
    {
        float* s_cq = (float*)sm_raw;   // [64][8]
        for (int u = bx; u < 17 * 2 * NZ2; u += nb) {
            int cx = u % 17, bg = (u / 17) & 1, z = u / 34;
            int i0 = z * 64, b0 = bg * 8;
            for (int idx = tid; idx < 512; idx += 256) {
                int i = idx >> 3, b = idx & 7;
                s_cq[idx] = g_cq[b0 + b][i0 + i];
            }
            __syncthreads();
            int col = cx * 256 + tid;
            if (col < T2DIM) {
                const float* W; int stride, c;
                if (col < 3072)      { W = w_uq_qr;    stride = 3072; c = col; }
                else if (col < 4096) { W = w_idx_qb;   stride = 1024; c = col - 3072; }
                else                 { W = w_idx_proj; stride = 8;    c = col - 4096; }
                const float* wp = W + (size_t)i0 * stride + c;
                float acc[8];
                #pragma unroll
                for (int b = 0; b < 8; b++) acc[b] = 0.f;
                #pragma unroll 8
                for (int i = 0; i < 64; i++) {
                    float w = wp[(size_t)i * stride];
                    float4 xa = *(const float4*)&s_cq[i * 8 + 0];
                    float4 xb = *(const float4*)&s_cq[i * 8 + 4];
                    acc[0] += xa.x * w; acc[1] += xa.y * w; acc[2] += xa.z * w; acc[3] += xa.w * w;
                    acc[4] += xb.x * w; acc[5] += xb.y * w; acc[6] += xb.z * w; acc[7] += xb.w * w;
                }
                float* dst;
                if (col < 3072)      dst = &g_q[0][col];
                else if (col < 4096) dst = &g_qi[0][col - 3072];
                else                 dst = &g_hw[0][col - 4096];
                int bstride = (col < 3072) ? NH * 192 : (col < 4096 ? NIH * IDXD : NIH);
                #pragma unroll
                for (int b = 0; b < 8; b++)
                    atomicAdd(dst + (size_t)(b0 + b) * bstride, acc[b]);
            }
            __syncthreads();
        }
    }
    gsync(2, nb);

    // ===== P3: iscore (512 units), 2 rows in flight per warp =====
    {
        float* s_qi = (float*)sm_raw;
        float* s_hw = (float*)(sm_raw + 4096);
        for (int u = bx; u < 512; u += nb) {
            int chunk = u & 31, b = u >> 5;
            for (int i = tid; i < NIH * IDXD; i += 256) s_qi[i] = g_qi[b][i];
            if (tid < NIH) s_hw[tid] = g_hw[b][tid];
            __syncthreads();
            int warp = tid >> 5, lane = tid & 31;
            int act = act_seqs[b];
            int ci = cidx[b];
            for (int rr = warp * 2; rr < 128; rr += 16) {
                int n0 = chunk * 128 + rr;
                int n1 = n0 + 1;
                bool v0 = n0 < act, v1 = n1 < act;
                const float* p0;
                const float* p1;
                {
                    int blk = bt[b * BPS + (n0 >> 7)];
                    long f0 = (long)blk * BLKSZ + (n0 & 127);
                    long f1 = f0 + 1;
                    p0 = (!v0 || f0 == (long)ci) ? g_ki[b] : ikc + f0 * IDXD;
                    p1 = (!v1 || f1 == (long)ci) ? g_ki[b] : ikc + f1 * IDXD;
                }
                float4 kv0 = *(const float4*)(p0 + lane * 4);
                float4 kv1 = *(const float4*)(p1 + lane * 4);
                float acc0[NIH], acc1[NIH];
                #pragma unroll
                for (int h = 0; h < NIH; h++) {
                    float4 q = *(const float4*)&s_qi[h * IDXD + lane * 4];
                    acc0[h] = kv0.x * q.x + kv0.y * q.y + kv0.z * q.z + kv0.w * q.w;
                    acc1[h] = kv1.x * q.x + kv1.y * q.y + kv1.z * q.z + kv1.w * q.w;
                }
                #pragma unroll
                for (int off = 16; off; off >>= 1) {
                    #pragma unroll
                    for (int h = 0; h < NIH; h++) {
                        acc0[h] += __shfl_xor_sync(0xffffffffu, acc0[h], off);
                        acc1[h] += __shfl_xor_sync(0xffffffffu, acc1[h], off);
                    }
                }
                if (lane == 0) {
                    float s0 = 0.f, s1 = 0.f;
                    #pragma unroll
                    for (int h = 0; h < NIH; h++) {
                        s0 += s_hw[h] * fmaxf(acc0[h], 0.f);
                        s1 += s_hw[h] * fmaxf(acc1[h], 0.f);
                    }
                    g_isc[b][n0] = v0 ? s0 * IDX_SCALE : -1e9f;
                    g_isc[b][n1] = v1 ? s1 * IDX_SCALE : -1e9f;
                }
            }
            __syncthreads();
        }
    }
    gsync(3, nb);

    // ===== P4: topk (16 units) + qprep (64 units) overlapped =====
    {
        for (int u = bx; u < 16 + 64; u += nb) {
            if (u < 16) {
                unsigned* s_key  = (unsigned*)sm_raw;
                unsigned* s_hist = (unsigned*)(sm_raw + 16384);
                unsigned* s_scan = (unsigned*)(sm_raw + 17408);
                unsigned* s_bm   = (unsigned*)(sm_raw + 18432);
                unsigned* s_cnt  = (unsigned*)(sm_raw + 18944);
                unsigned* s_pref = (unsigned*)(sm_raw + 18948);
                int*      s_rem  = (int*)(sm_raw + 18952);
                int*      s_Bw   = (int*)(sm_raw + 18956);
                int*      s_need = (int*)(sm_raw + 18960);
                int b = u;
                int act = act_seqs[b];
                for (int i = tid; i < MAXKV; i += 256) {
                    float v = (i < act) ? g_isc[b][i] : -1e9f;
                    unsigned uu = __float_as_uint(v);
                    uu = (uu & 0x80000000u) ? ~uu : (uu | 0x80000000u);
                    s_key[i] = uu;
                }
                if (tid == 0) { *s_cnt = 0; *s_rem = TOPK; *s_pref = 0; }
                __syncthreads();
                for (int level = 0; level < 4; level++) {
                    int shift = 24 - level * 8;
                    s_hist[tid] = 0;
                    __syncthreads();
                    unsigned pref = *s_pref;
                    for (int i = tid; i < MAXKV; i += 256) {
                        unsigned uu = s_key[i];
                        if (level == 0 || (uu >> (shift + 8)) == pref)
                            atomicAdd(&s_hist[(uu >> shift) & 255u], 1u);
                    }
                    __syncthreads();
                    s_scan[tid] = s_hist[tid];
                    __syncthreads();
                    #pragma unroll
                    for (int off = 1; off < 256; off <<= 1) {
                        unsigned t = (tid + off < 256) ? s_scan[tid + off] : 0u;
                        __syncthreads();
                        s_scan[tid] += t;
                        __syncthreads();
                    }
                    int rem = *s_rem;
                    unsigned cumGT = s_scan[tid] - s_hist[tid];
                    if ((int)cumGT < rem && (int)s_scan[tid] >= rem) {
                        *s_pref = (pref << 8) | (unsigned)tid;
                        *s_rem = rem - (int)cumGT;
                    }
                    __syncthreads();
                }
                unsigned K = *s_pref;
                for (int i = tid; i < MAXKV; i += 256) {
                    if (s_key[i] > K) {
                        unsigned pos = atomicAdd(s_cnt, 1u);
                        g_sel[b][pos] = i;
                        g_selval[b][pos] = (i < act) ? g_isc[b][i] : -1e9f;
                    }
                }
                for (int w = tid; w < MAXKV / 32; w += 256) s_bm[w] = 0;
                __syncthreads();
                for (int i = tid; i < MAXKV; i += 256)
                    if (s_key[i] == K) atomicOr(&s_bm[i >> 5], 1u << (i & 31));
                __syncthreads();
                if (tid == 0) {
                    int need = *s_rem;
                    int w = 0;
                    for (; w < MAXKV / 32; w++) {
                        int pc = __popc(s_bm[w]);
                        if (pc >= need) break;
                        need -= pc;
                    }
                    *s_Bw = w; *s_need = need;
                }
                __syncthreads();
                int Bw = *s_Bw, need = *s_need;
                for (int i = tid; i < MAXKV; i += 256) {
                    if (s_key[i] == K) {
                        int w = i >> 5, bit = i & 31;
                        bool take = (w < Bw) ||
                                    (w == Bw && (int)__popc(s_bm[w] & ((1u << bit) - 1u)) < need);
                        if (take) {
                            unsigned pos = atomicAdd(s_cnt, 1u);
                            g_sel[b][pos] = i;
                            g_selval[b][pos] = (i < act) ? g_isc[b][i] : -1e9f;
                        }
                    }
                }
                __syncthreads();
            } else {
                int u2 = u - 16;
                int h = u2 & 15, r = u2 >> 4;
                int cc = r & 1, bg = r >> 1;
                int b0 = bg * 8;
                float* s_qn = (float*)sm_raw;  // [128][8] transposed
                for (int idx = tid; idx < 1024; idx += 256) {
                    int d = idx >> 3, bb = idx & 7;
                    s_qn[idx] = g_q[b0 + bb][h * 192 + d];
                }
                if (cc == 0) {
                    for (int idx = tid; idx < 512; idx += 256) {
                        int bb = idx >> 6, d = idx & 63;
                        int b = b0 + bb;
                        float v = g_q[b][h * 192 + DN + d];
                        float rot = (d < 32) ? -g_q[b][h * 192 + DN + d + 32] : g_q[b][h * 192 + DN + d - 32];
                        g_qpe[b][h][d] = v * cosp[b * DR + d] + rot * sinp[b * DR + d];
                    }
                }
                __syncthreads();
                int c = cc * 256 + tid;
                const float* wk = w_uk + (size_t)h * DN * KVL + c;
                float acc[8];
                #pragma unroll
                for (int b = 0; b < 8; b++) acc[b] = 0.f;
                #pragma unroll 8
                for (int d = 0; d < DN; d++) {
                    float w = wk[(size_t)d * KVL];
                    float4 xa = *(const float4*)&s_qn[d * 8 + 0];
                    float4 xb = *(const float4*)&s_qn[d * 8 + 4];
                    acc[0] += xa.x * w; acc[1] += xa.y * w; acc[2] += xa.z * w; acc[3] += xa.w * w;
                    acc[4] += xb.x * w; acc[5] += xb.y * w; acc[6] += xb.z * w; acc[7] += xb.w * w;
                }
                #pragma unroll
                for (int b = 0; b < 8; b++) g_qlat[b0 + b][h][c] = acc[b];
                __syncthreads();
            }
        }
    }
    gsync(4, nb);

    // ===== P5: attention partials — online softmax, smem-staged KV (256 units) =====
    {
        float* s_qlat = (float*)sm_raw;                       // 32768 B
        float* s_qpe  = (float*)(sm_raw + 32768);             //  4096 B
        float* s_kv   = (float*)(sm_raw + 36864);             // 16384 B (8 rows x 512)
        float* s_kr   = (float*)(sm_raw + 53248);             //  2048 B (8 rows x 64)
        float* s_sc   = (float*)(sm_raw + 55296);             //   512 B (8 x 16)
        float* s_m    = (float*)(sm_raw + 55808);
        float* s_l    = (float*)(sm_raw + 55872);
        float* s_fac  = (float*)(sm_raw + 55936);
        const float** s_ckvp = (const float**)(sm_raw + 56064);
        const float** s_krp  = (const float**)(sm_raw + 56576);
        int* s_vld = (int*)(sm_raw + 57088);
        for (int u = bx; u < NSPLIT * BS; u += nb) {
            int s = u & 15, b = u >> 4;
            const float4* qlb = (const float4*)&g_qlat[b][0][0];
            for (int i = tid; i < NH * KVL / 4; i += 256) ((float4*)s_qlat)[i] = qlb[i];
            const float4* qpb = (const float4*)&g_qpe[b][0][0];
            for (int i = tid; i < NH * DR / 4; i += 256) ((float4*)s_qpe)[i] = qpb[i];
            if (tid < SPLITROWS) {
                int j = tid;
                int n = g_sel[b][s * SPLITROWS + j];
                float v = g_selval[b][s * SPLITROWS + j];
                bool valid = v > -1e8f;
                const float* cp; const float* kp;
                if (!valid) { cp = g_ckv[b]; kp = g_kr[b]; }
                else {
                    int blk = bt[b * BPS + (n >> 7)];
                    long flat = (long)blk * BLKSZ + (n & 127);
                    if (flat == (long)cidx[b]) { cp = g_ckv[b]; kp = g_kr[b]; }
                    else { cp = kvc + flat * KVL; kp = krc + flat * DR; }
                }
                s_ckvp[j] = cp; s_krp[j] = kp; s_vld[j] = valid ? 1 : 0;
            }
            if (tid < NH) { s_m[tid] = -1e30f; s_l[tid] = 0.f; }
            float o0[NH], o1[NH];
            #pragma unroll
            for (int h = 0; h < NH; h++) { o0[h] = 0.f; o1[h] = 0.f; }
            __syncthreads();
            int warp = tid >> 5, lane = tid & 31;
            for (int g = 0; g < SPLITROWS / 8; g++) {
                #pragma unroll
                for (int k = 0; k < 4; k++) {
                    int f = tid + 256 * k;
                    int r = f >> 7, pos = f & 127;
                    ((float4*)&s_kv[r * 512])[pos] = ((const float4*)s_ckvp[g * 8 + r])[pos];
                }
                if (tid < 128) {
                    int r = tid >> 4, pos = tid & 15;
                    ((float4*)&s_kr[r * 64])[pos] = ((const float4*)s_krp[g * 8 + r])[pos];
                }
                __syncthreads();
                {
                    int j = warp;
                    float acc[NH];
                    #pragma unroll
                    for (int h = 0; h < NH; h++) acc[h] = 0.f;
                    #pragma unroll
                    for (int q = 0; q < 4; q++) {
                        float4 v = *(const float4*)&s_kv[j * 512 + 4 * (lane + 32 * q)];
                        #pragma unroll
                        for (int h = 0; h < NH; h++) {
                            float4 ql = *(const float4*)&s_qlat[h * KVL + 4 * (lane + 32 * q)];
                            acc[h] += v.x * ql.x + v.y * ql.y + v.z * ql.z + v.w * ql.w;
                        }
                    }
                    float2 kv2 = *(const float2*)&s_kr[j * 64 + 2 * lane];
                    #pragma unroll
                    for (int h = 0; h < NH; h++) {
                        float2 qp = *(const float2*)&s_qpe[h * DR + 2 * lane];
                        acc[h] += kv2.x * qp.x + kv2.y * qp.y;
                    }
                    #pragma unroll
                    for (int off = 16; off; off >>= 1) {
                        #pragma unroll
                        for (int h = 0; h < NH; h++)
                            acc[h] += __shfl_xor_sync(0xffffffffu, acc[h], off);
                    }
                    if (lane == 0) {
                        bool valid = s_vld[g * 8 + j] != 0;
                        #pragma unroll
                        for (int h = 0; h < NH; h++)
                            s_sc[j * NH + h] = valid ? acc[h] * ATT_SCALE : -1e9f;
                    }
                }
                __syncthreads();
                #pragma unroll
                for (int hh = warp; hh < NH; hh += 8) {
                    float sc = (lane < 8) ? s_sc[lane * NH + hh] : -3.0e38f;
                    float gm = sc;
                    #pragma unroll
                    for (int off = 4; off; off >>= 1) gm = fmaxf(gm, __shfl_xor_sync(0xffffffffu, gm, off));
                    float oldm = s_m[hh];
                    float newm = fmaxf(oldm, gm);
                    float p = (lane < 8) ? __expf(sc - newm) : 0.f;
                    float sl = p;
                    #pragma unroll
                    for (int off = 4; off; off >>= 1) sl += __shfl_xor_sync(0xffffffffu, sl, off);
                    if (lane < 8) s_sc[lane * NH + hh] = p;
                    if (lane == 0) {
                        float fac = __expf(oldm - newm);
                        s_m[hh] = newm;
                        s_l[hh] = s_l[hh] * fac + sl;
                        s_fac[hh] = fac;
                    }
                }
                __syncthreads();
                {
                    float4 f0 = *(const float4*)&s_fac[0];
                    float4 f1 = *(const float4*)&s_fac[4];
                    float4 f2 = *(const float4*)&s_fac[8];
                    float4 f3 = *(const float4*)&s_fac[12];
                    o0[0]  *= f0.x; o0[1]  *= f0.y; o0[2]  *= f0.z; o0[3]  *= f0.w;
                    o0[4]  *= f1.x; o0[5]  *= f1.y; o0[6]  *= f1.z; o0[7]  *= f1.w;
                    o0[8]  *= f2.x; o0[9]  *= f2.y; o0[10] *= f2.z; o0[11] *= f2.w;
                    o0[12] *= f3.x; o0[13] *= f3.y; o0[14] *= f3.z; o0[15] *= f3.w;
                    o1[0]  *= f0.x; o1[1]  *= f0.y; o1[2]  *= f0.z; o1[3]  *= f0.w;
                    o1[4]  *= f1.x; o1[5]  *= f1.y; o1[6]  *= f1.z; o1[7]  *= f1.w;
                    o1[8]  *= f2.x; o1[9]  *= f2.y; o1[10] *= f2.z; o1[11] *= f2.w;
                    o1[12] *= f3.x; o1[13] *= f3.y; o1[14] *= f3.z; o1[15] *= f3.w;
                    int c0 = tid, c1 = tid + 256;
                    #pragma unroll
                    for (int j = 0; j < 8; j++) {
                        float va = s_kv[j * 512 + c0];
                        float vb = s_kv[j * 512 + c1];
                        float4 p0 = *(const float4*)&s_sc[j * NH + 0];
                        float4 p1 = *(const float4*)&s_sc[j * NH + 4];
                        float4 p2 = *(const float4*)&s_sc[j * NH + 8];
                        float4 p3 = *(const float4*)&s_sc[j * NH + 12];
                        o0[0]  += p0.x * va; o0[1]  += p0.y * va; o0[2]  += p0.z * va; o0[3]  += p0.w * va;
                        o0[4]  += p1.x * va; o0[5]  += p1.y * va; o0[6]  += p1.z * va; o0[7]  += p1.w * va;
                        o0[8]  += p2.x * va; o0[9]  += p2.y * va; o0[10] += p2.z * va; o0[11] += p2.w * va;
                        o0[12] += p3.x * va; o0[13] += p3.y * va; o0[14] += p3.z * va; o0[15] += p3.w * va;
                        o1[0]  += p0.x * vb; o1[1]  += p0.y * vb; o1[2]  += p0.z * vb; o1[3]  += p0.w * vb;
                        o1[4]  += p1.x * vb; o1[5]  += p1.y * vb; o1[6]  += p1.z * vb; o1[7]  += p1.w * vb;
                        o1[8]  += p2.x * vb; o1[9]  += p2.y * vb; o1[10] += p2.z * vb; o1[11] += p2.w * vb;
                        o1[12] += p3.x * vb; o1[13] += p3.y * vb; o1[14] += p3.z * vb; o1[15] += p3.w * vb;
                    }
                }
                __syncthreads();
            }
            if (tid < NH) { g_m[b][s][tid] = s_m[tid]; g_l[b][s][tid] = s_l[tid]; }
            {
                int c0 = tid, c1 = tid + 256;
                #pragma unroll
                for (int h = 0; h < NH; h++) {
                    g_op[b][s][h][c0] = o0[h];
                    g_op[b][s][h][c1] = o1[h];
                }
            }
            __syncthreads();
        }
    }
    gsync(5, nb);

    // ===== P6: combine + output projection (float4) =====
    {
        float* s_olat = (float*)sm_raw;
        float* s_w    = (float*)(sm_raw + 2048);
        float* s_invl = (float*)(sm_raw + 2112);
        for (int u = bx; u < NH * BS; u += nb) {
            int h = u & 15, b = u >> 4;
            if (tid == 0) {
                float M = -1e30f;
                for (int s = 0; s < NSPLIT; s++) M = fmaxf(M, g_m[b][s][h]);
                float L = 0.f;
                for (int s = 0; s < NSPLIT; s++) {
                    float w = __expf(g_m[b][s][h] - M);
                    s_w[s] = w;
                    L += g_l[b][s][h] * w;
                }
                *s_invl = 1.f / L;
            }
            __syncthreads();
            if (tid < 128) {
                int c4 = tid;  // float4 index, 128 x 4 = 512
                float4 a = make_float4(0.f, 0.f, 0.f, 0.f);
                #pragma unroll
                for (int s = 0; s < NSPLIT; s++) {
                    float4 v = ((const float4*)&g_op[b][s][h][0])[c4];
                    float w = s_w[s];
                    a.x += v.x * w; a.y += v.y * w; a.z += v.z * w; a.w += v.w * w;
                }
                float il = *s_invl;
                a.x *= il; a.y *= il; a.z *= il; a.w *= il;
                ((float4*)s_olat)[c4] = a;
            }
            __syncthreads();
            if (tid < DN) {
                int d = tid;
                const float* wk = w_uk + ((size_t)(h * DN + d)) * KVL;
                float a = 0.f;
                #pragma unroll 8
                for (int c = 0; c < KVL; c += 4) {
                    float4 o4 = *(const float4*)&s_olat[c];
                    float4 w4 = *(const float4*)&wk[c];
                    a += o4.x * w4.x + o4.y * w4.y + o4.z * w4.z + o4.w * w4.w;
                }
                out[b * (NH * DN) + h * DN + d] = a;
            }
            __syncthreads();
        }
    }

    // reset sync state for next graph replay
    __syncthreads();
    if (tid == 0) {
        __threadfence();
        unsigned a = atomicAdd(&g_ack, 1u) + 1;
        if (a == (unsigned)nb) {
            #pragma unroll
            for (int i = 0; i < 8; i++) g_barcnt[i] = 0;
            g_ack = 0;
            __threadfence();
        }
    }
}

// ---------------- launch ----------------
extern "C" void kernel_launch(void* const* d_in, const int* in_sizes, int n_in,
                              void* d_out, int out_size) {
    const float* x            = (const float*)d_in[0];
    const float* w_dq         = (const float*)d_in[1];
    const float* w_uq_qr      = (const float*)d_in[2];
    const float* w_uk         = (const float*)d_in[3];
    const float* w_dkv_kr     = (const float*)d_in[4];
    const float* gamma_cq     = (const float*)d_in[5];
    const float* gamma_ckv    = (const float*)d_in[6];
    const float* sinp         = (const float*)d_in[7];
    const float* cosp         = (const float*)d_in[8];
    const int*   cache_index  = (const int*)d_in[9];
    const float* kv_cache     = (const float*)d_in[10];
    const float* kr_cache     = (const float*)d_in[11];
    const int*   block_table  = (const int*)d_in[12];
    const int*   act_seqs     = (const int*)d_in[13];
    const float* w_idx_qb     = (const float*)d_in[14];
    const float* w_idx_k      = (const float*)d_in[15];
    const float* w_idx_proj   = (const float*)d_in[16];
    const float* in_gamma_k   = (const float*)d_in[17];
    const float* in_beta_k    = (const float*)d_in[18];
    const float* index_k_cache= (const float*)d_in[19];
    float* out = (float*)d_out;

    cudaFuncSetAttribute(k_mega, cudaFuncAttributeMaxDynamicSharedMemorySize, SMSZ);

    int sms = 148, bpm = 0;
    cudaDeviceGetAttribute(&sms, cudaDevAttrMultiProcessorCount, 0);
    cudaOccupancyMaxActiveBlocksPerMultiprocessor(&bpm, k_mega, 256, SMSZ);
    if (bpm < 1) bpm = 1;
    int nb = bpm * sms;
    if (nb > NBMAX) nb = NBMAX;

    k_mega<<<nb, 256, SMSZ>>>(x, w_dq, w_uq_qr, w_uk, w_dkv_kr, gamma_cq, gamma_ckv,
                              sinp, cosp, cache_index, kv_cache, kr_cache, block_table,
                              act_seqs, w_idx_qb, w_idx_k, w_idx_proj, in_gamma_k,
                              in_beta_k, index_k_cache, out, nb);
}

// round 12
// speedup vs baseline: 1.3262x; 1.3262x over previous
#include <cuda_runtime.h>
#include <cuda_bf16.h>
#include <math.h>

#define BS 16
#define HDIM 2048
#define QL 768
#define KVL 512
#define DR 64
#define DN 128
#define NH 16
#define NIH 8
#define IDXD 128
#define BLKSZ 128
#define BPS 32
#define MAXKV 4096
#define TOPK 1024
#define NSPLIT 16
#define SPLITROWS 64

#define NZ1 32          /* stage1 K-slices of 64 */
#define NZ2 12          /* stage2 K-slices of 64 */
#define T1DIM 1472
#define T2DIM 4104

#define ATT_SCALE 0.07216878364870323f
#define IDX_SCALE 0.08838834764831845f

#define NBMAX 448
#define SMSZ 57344

// ---------------- scratch ----------------
__device__ float g_t1p[NZ1][BS][T1DIM];
__device__ float g_t2p[NZ2][BS][T2DIM];
__device__ float g_cq[BS][QL];
__device__ float g_ckv[BS][KVL];
__device__ float g_kr[BS][DR];
__device__ float g_ki[BS][IDXD];
__device__ float g_q[BS][NH * 192];
__device__ float g_qi[BS][NIH * IDXD];
__device__ float g_hw[BS][NIH];
__device__ float g_qpe[BS][NH][DR];
__device__ float g_qlat[BS][NH][KVL];
__device__ float g_isc[BS][MAXKV];
__device__ int   g_sel[BS][TOPK];
__device__ float g_selval[BS][TOPK];
__device__ float g_m[BS][NSPLIT][NH];
__device__ float g_l[BS][NSPLIT][NH];
__device__ float g_op[BS][NSPLIT][NH][KVL];

__device__ unsigned g_barcnt[8];
__device__ unsigned g_ack;

__device__ __forceinline__ void gsync(int id, int nb) {
    __syncthreads();
    if (threadIdx.x == 0) {
        __threadfence();
        atomicAdd(&g_barcnt[id], 1u);
        while (*(volatile unsigned*)&g_barcnt[id] < (unsigned)nb) { __nanosleep(64); }
    }
    __syncthreads();
}

__device__ __forceinline__ float blockSum256(float v, float* buf) {
    int tid = threadIdx.x;
    buf[tid] = v;
    __syncthreads();
    for (int s = 128; s > 0; s >>= 1) {
        if (tid < s) buf[tid] += buf[tid + s];
        __syncthreads();
    }
    float r = buf[0];
    __syncthreads();
    return r;
}

__global__ void __launch_bounds__(256, 3)
k_mega(const float* __restrict__ x, const float* __restrict__ w_dq,
       const float* __restrict__ w_uq_qr, const float* __restrict__ w_uk,
       const float* __restrict__ w_dkv, const float* __restrict__ gamma_cq,
       const float* __restrict__ gamma_ckv, const float* __restrict__ sinp,
       const float* __restrict__ cosp, const int* __restrict__ cidx,
       const float* __restrict__ kvc, const float* __restrict__ krc,
       const int* __restrict__ bt, const int* __restrict__ act_seqs,
       const float* __restrict__ w_idx_qb, const float* __restrict__ w_idxk,
       const float* __restrict__ w_idx_proj, const float* __restrict__ in_g,
       const float* __restrict__ in_b, const float* __restrict__ ikc,
       float* __restrict__ out, int nb)
{
    extern __shared__ __align__(16) char sm_raw[];
    int tid = threadIdx.x;
    int bx = blockIdx.x;

    // ===== P0: stage1 partials, 8 batches/unit, transposed smem [k][b] (384 units) =====
    {
        float* s_x = (float*)sm_raw;   // [64][8]
        for (int u = bx; u < 6 * 2 * NZ1; u += nb) {
            int cx = u % 6, bg = (u / 6) & 1, z = u / 12;
            int i0 = z * 64, b0 = bg * 8;
            for (int idx = tid; idx < 512; idx += 256) {
                int i = idx >> 3, b = idx & 7;
                s_x[idx] = x[(b0 + b) * HDIM + i0 + i];
            }
            __syncthreads();
            int col = cx * 256 + tid;
            if (col < T1DIM) {
                const float* W; int stride, c;
                if (col < QL)                 { W = w_dq;   stride = QL;       c = col; }
                else if (col < QL + KVL + DR) { W = w_dkv;  stride = KVL + DR; c = col - QL; }
                else                          { W = w_idxk; stride = IDXD;     c = col - (QL + KVL + DR); }
                const float* wp = W + (size_t)i0 * stride + c;
                float acc[8];
                #pragma unroll
                for (int b = 0; b < 8; b++) acc[b] = 0.f;
                #pragma unroll 8
                for (int i = 0; i < 64; i++) {
                    float w = wp[(size_t)i * stride];
                    float4 xa = *(const float4*)&s_x[i * 8 + 0];
                    float4 xb = *(const float4*)&s_x[i * 8 + 4];
                    acc[0] += xa.x * w; acc[1] += xa.y * w; acc[2] += xa.z * w; acc[3] += xa.w * w;
                    acc[4] += xb.x * w; acc[5] += xb.y * w; acc[6] += xb.z * w; acc[7] += xb.w * w;
                }
                #pragma unroll
                for (int b = 0; b < 8; b++) g_t1p[z][b0 + b][col] = acc[b];
            }
            __syncthreads();
        }
    }
    gsync(0, nb);

    // ===== P1: norms + rope(kr) =====
    {
        float* s_t  = (float*)sm_raw;
        float* sred = (float*)(sm_raw + T1DIM * 4 + 64);
        for (int u = bx; u < BS; u += nb) {
            int b = u;
            for (int i = tid; i < T1DIM; i += 256) {
                float a = 0.f;
                #pragma unroll
                for (int z = 0; z < NZ1; z++) a += g_t1p[z][b][i];
                s_t[i] = a;
            }
            __syncthreads();
            float ss = 0.f;
            for (int i = tid; i < QL; i += 256) ss += s_t[i] * s_t[i];
            ss = blockSum256(ss, sred);
            float r = rsqrtf(ss / (float)QL + 1e-6f);
            for (int i = tid; i < QL; i += 256) g_cq[b][i] = s_t[i] * r * gamma_cq[i];
            float s2 = 0.f;
            for (int i = tid; i < KVL; i += 256) { float v = s_t[QL + i]; s2 += v * v; }
            s2 = blockSum256(s2, sred);
            float r2 = rsqrtf(s2 / (float)KVL + 1e-6f);
            for (int i = tid; i < KVL; i += 256) g_ckv[b][i] = s_t[QL + i] * r2 * gamma_ckv[i];
            if (tid < DR) {
                int d = tid;
                float v = s_t[QL + KVL + d];
                float rot = (d < 32) ? -s_t[QL + KVL + d + 32] : s_t[QL + KVL + d - 32];
                g_kr[b][d] = v * cosp[b * DR + d] + rot * sinp[b * DR + d];
            }
            float sm = 0.f;
            for (int i = tid; i < IDXD; i += 256) sm += s_t[QL + KVL + DR + i];
            sm = blockSum256(sm, sred);
            float mean = sm / (float)IDXD;
            float sv = 0.f;
            for (int i = tid; i < IDXD; i += 256) { float c = s_t[QL + KVL + DR + i] - mean; sv += c * c; }
            sv = blockSum256(sv, sred);
            float rv = rsqrtf(sv / (float)IDXD + 1e-6f);
            for (int i = tid; i < IDXD; i += 256) {
                float c = s_t[QL + KVL + DR + i] - mean;
                g_ki[b][i] = c * rv * in_g[i] + in_b[i];
            }
            __syncthreads();
        }
    }
    gsync(1, nb);

    // ===== P2: stage2 partials, 8 batches/unit, transposed smem (408 units) =====
    {
        float* s_cq = (float*)sm_raw;   // [64][8]
        for (int u = bx; u < 17 * 2 * NZ2; u += nb) {
            int cx = u % 17, bg = (u / 17) & 1, z = u / 34;
            int i0 = z * 64, b0 = bg * 8;
            for (int idx = tid; idx < 512; idx += 256) {
                int i = idx >> 3, b = idx & 7;
                s_cq[idx] = g_cq[b0 + b][i0 + i];
            }
            __syncthreads();
            int col = cx * 256 + tid;
            if (col < T2DIM) {
                const float* W; int stride, c;
                if (col < 3072)      { W = w_uq_qr;    stride = 3072; c = col; }
                else if (col < 4096) { W = w_idx_qb;   stride = 1024; c = col - 3072; }
                else                 { W = w_idx_proj; stride = 8;    c = col - 4096; }
                const float* wp = W + (size_t)i0 * stride + c;
                float acc[8];
                #pragma unroll
                for (int b = 0; b < 8; b++) acc[b] = 0.f;
                #pragma unroll 8
                for (int i = 0; i < 64; i++) {
                    float w = wp[(size_t)i * stride];
                    float4 xa = *(const float4*)&s_cq[i * 8 + 0];
                    float4 xb = *(const float4*)&s_cq[i * 8 + 4];
                    acc[0] += xa.x * w; acc[1] += xa.y * w; acc[2] += xa.z * w; acc[3] += xa.w * w;
                    acc[4] += xb.x * w; acc[5] += xb.y * w; acc[6] += xb.z * w; acc[7] += xb.w * w;
                }
                #pragma unroll
                for (int b = 0; b < 8; b++) g_t2p[z][b0 + b][col] = acc[b];
            }
            __syncthreads();
        }
    }
    gsync(2, nb);

    // ===== P2b: reduce stage2 partials =====
    {
        int total = BS * T2DIM;
        for (int idx = bx * 256 + tid; idx < total; idx += nb * 256) {
            int b = idx / T2DIM, col = idx % T2DIM;
            float a = 0.f;
            #pragma unroll
            for (int z = 0; z < NZ2; z++) a += g_t2p[z][b][col];
            if (col < 3072)      g_q[b][col] = a;
            else if (col < 4096) g_qi[b][col - 3072] = a;
            else                 g_hw[b][col - 4096] = a;
        }
    }
    gsync(3, nb);

    // ===== P3: iscore (512 units) =====
    {
        float* s_qi = (float*)sm_raw;
        float* s_hw = (float*)(sm_raw + 4096);
        for (int u = bx; u < 512; u += nb) {
            int chunk = u & 31, b = u >> 5;
            for (int i = tid; i < NIH * IDXD; i += 256) s_qi[i] = g_qi[b][i];
            if (tid < NIH) s_hw[tid] = g_hw[b][tid];
            __syncthreads();
            int warp = tid >> 5, lane = tid & 31;
            int act = act_seqs[b];
            int ci = cidx[b];
            for (int r = warp; r < 128; r += 8) {
                int n = chunk * 128 + r;
                if (n >= act) { if (lane == 0) g_isc[b][n] = -1e9f; continue; }
                int blk = bt[b * BPS + (n >> 7)];
                long flat = (long)blk * BLKSZ + (n & 127);
                const float* kr = (flat == (long)ci) ? g_ki[b] : ikc + flat * IDXD;
                float4 kv = *(const float4*)(kr + lane * 4);
                float acc[NIH];
                #pragma unroll
                for (int h = 0; h < NIH; h++) {
                    float4 q = *(const float4*)&s_qi[h * IDXD + lane * 4];
                    acc[h] = kv.x * q.x + kv.y * q.y + kv.z * q.z + kv.w * q.w;
                }
                #pragma unroll
                for (int off = 16; off; off >>= 1) {
                    #pragma unroll
                    for (int h = 0; h < NIH; h++)
                        acc[h] += __shfl_xor_sync(0xffffffffu, acc[h], off);
                }
                if (lane == 0) {
                    float s = 0.f;
                    #pragma unroll
                    for (int h = 0; h < NIH; h++) s += s_hw[h] * fmaxf(acc[h], 0.f);
                    g_isc[b][n] = s * IDX_SCALE;
                }
            }
            __syncthreads();
        }
    }
    gsync(4, nb);

    // ===== P4: topk (16 units) + qprep (64 units) overlapped =====
    {
        for (int u = bx; u < 16 + 64; u += nb) {
            if (u < 16) {
                unsigned* s_key  = (unsigned*)sm_raw;
                unsigned* s_hist = (unsigned*)(sm_raw + 16384);
                unsigned* s_scan = (unsigned*)(sm_raw + 17408);
                unsigned* s_bm   = (unsigned*)(sm_raw + 18432);
                unsigned* s_cnt  = (unsigned*)(sm_raw + 18944);
                unsigned* s_pref = (unsigned*)(sm_raw + 18948);
                int*      s_rem  = (int*)(sm_raw + 18952);
                int*      s_Bw   = (int*)(sm_raw + 18956);
                int*      s_need = (int*)(sm_raw + 18960);
                int b = u;
                int act = act_seqs[b];
                for (int i = tid; i < MAXKV; i += 256) {
                    float v = (i < act) ? g_isc[b][i] : -1e9f;
                    unsigned uu = __float_as_uint(v);
                    uu = (uu & 0x80000000u) ? ~uu : (uu | 0x80000000u);
                    s_key[i] = uu;
                }
                if (tid == 0) { *s_cnt = 0; *s_rem = TOPK; *s_pref = 0; }
                __syncthreads();
                for (int level = 0; level < 4; level++) {
                    int shift = 24 - level * 8;
                    s_hist[tid] = 0;
                    __syncthreads();
                    unsigned pref = *s_pref;
                    for (int i = tid; i < MAXKV; i += 256) {
                        unsigned uu = s_key[i];
                        if (level == 0 || (uu >> (shift + 8)) == pref)
                            atomicAdd(&s_hist[(uu >> shift) & 255u], 1u);
                    }
                    __syncthreads();
                    s_scan[tid] = s_hist[tid];
                    __syncthreads();
                    #pragma unroll
                    for (int off = 1; off < 256; off <<= 1) {
                        unsigned t = (tid + off < 256) ? s_scan[tid + off] : 0u;
                        __syncthreads();
                        s_scan[tid] += t;
                        __syncthreads();
                    }
                    int rem = *s_rem;
                    unsigned cumGT = s_scan[tid] - s_hist[tid];
                    if ((int)cumGT < rem && (int)s_scan[tid] >= rem) {
                        *s_pref = (pref << 8) | (unsigned)tid;
                        *s_rem = rem - (int)cumGT;
                    }
                    __syncthreads();
                }
                unsigned K = *s_pref;
                for (int i = tid; i < MAXKV; i += 256) {
                    if (s_key[i] > K) {
                        unsigned pos = atomicAdd(s_cnt, 1u);
                        g_sel[b][pos] = i;
                        g_selval[b][pos] = (i < act) ? g_isc[b][i] : -1e9f;
                    }
                }
                for (int w = tid; w < MAXKV / 32; w += 256) s_bm[w] = 0;
                __syncthreads();
                for (int i = tid; i < MAXKV; i += 256)
                    if (s_key[i] == K) atomicOr(&s_bm[i >> 5], 1u << (i & 31));
                __syncthreads();
                if (tid == 0) {
                    int need = *s_rem;
                    int w = 0;
                    for (; w < MAXKV / 32; w++) {
                        int pc = __popc(s_bm[w]);
                        if (pc >= need) break;
                        need -= pc;
                    }
                    *s_Bw = w; *s_need = need;
                }
                __syncthreads();
                int Bw = *s_Bw, need = *s_need;
                for (int i = tid; i < MAXKV; i += 256) {
                    if (s_key[i] == K) {
                        int w = i >> 5, bit = i & 31;
                        bool take = (w < Bw) ||
                                    (w == Bw && (int)__popc(s_bm[w] & ((1u << bit) - 1u)) < need);
                        if (take) {
                            unsigned pos = atomicAdd(s_cnt, 1u);
                            g_sel[b][pos] = i;
                            g_selval[b][pos] = (i < act) ? g_isc[b][i] : -1e9f;
                        }
                    }
                }
                __syncthreads();
            } else {
                int u2 = u - 16;
                int h = u2 & 15, r = u2 >> 4;
                int cc = r & 1, bg = r >> 1;
                int b0 = bg * 8;
                float* s_qn = (float*)sm_raw;  // [128][8] transposed
                for (int idx = tid; idx < 1024; idx += 256) {
                    int d = idx >> 3, bb = idx & 7;
                    s_qn[idx] = g_q[b0 + bb][h * 192 + d];
                }
                if (cc == 0) {
                    for (int idx = tid; idx < 512; idx += 256) {
                        int bb = idx >> 6, d = idx & 63;
                        int b = b0 + bb;
                        float v = g_q[b][h * 192 + DN + d];
                        float rot = (d < 32) ? -g_q[b][h * 192 + DN + d + 32] : g_q[b][h * 192 + DN + d - 32];
                        g_qpe[b][h][d] = v * cosp[b * DR + d] + rot * sinp[b * DR + d];
                    }
                }
                __syncthreads();
                int c = cc * 256 + tid;
                const float* wk = w_uk + (size_t)h * DN * KVL + c;
                float acc[8];
                #pragma unroll
                for (int b = 0; b < 8; b++) acc[b] = 0.f;
                #pragma unroll 8
                for (int d = 0; d < DN; d++) {
                    float w = wk[(size_t)d * KVL];
                    float4 xa = *(const float4*)&s_qn[d * 8 + 0];
                    float4 xb = *(const float4*)&s_qn[d * 8 + 4];
                    acc[0] += xa.x * w; acc[1] += xa.y * w; acc[2] += xa.z * w; acc[3] += xa.w * w;
                    acc[4] += xb.x * w; acc[5] += xb.y * w; acc[6] += xb.z * w; acc[7] += xb.w * w;
                }
                #pragma unroll
                for (int b = 0; b < 8; b++) g_qlat[b0 + b][h][c] = acc[b];
                __syncthreads();
            }
        }
    }
    gsync(5, nb);

    // ===== P5: attention partials — online softmax, smem-staged KV (256 units) =====
    {
        float* s_qlat = (float*)sm_raw;                       // 32768 B
        float* s_qpe  = (float*)(sm_raw + 32768);             //  4096 B
        float* s_kv   = (float*)(sm_raw + 36864);             // 16384 B (8 rows x 512)
        float* s_kr   = (float*)(sm_raw + 53248);             //  2048 B (8 rows x 64)
        float* s_sc   = (float*)(sm_raw + 55296);             //   512 B (8 x 16)
        float* s_m    = (float*)(sm_raw + 55808);
        float* s_l    = (float*)(sm_raw + 55872);
        float* s_fac  = (float*)(sm_raw + 55936);
        const float** s_ckvp = (const float**)(sm_raw + 56064);
        const float** s_krp  = (const float**)(sm_raw + 56576);
        int* s_vld = (int*)(sm_raw + 57088);
        for (int u = bx; u < NSPLIT * BS; u += nb) {
            int s = u & 15, b = u >> 4;
            const float4* qlb = (const float4*)&g_qlat[b][0][0];
            for (int i = tid; i < NH * KVL / 4; i += 256) ((float4*)s_qlat)[i] = qlb[i];
            const float4* qpb = (const float4*)&g_qpe[b][0][0];
            for (int i = tid; i < NH * DR / 4; i += 256) ((float4*)s_qpe)[i] = qpb[i];
            if (tid < SPLITROWS) {
                int j = tid;
                int n = g_sel[b][s * SPLITROWS + j];
                float v = g_selval[b][s * SPLITROWS + j];
                bool valid = v > -1e8f;
                const float* cp; const float* kp;
                if (!valid) { cp = g_ckv[b]; kp = g_kr[b]; }
                else {
                    int blk = bt[b * BPS + (n >> 7)];
                    long flat = (long)blk * BLKSZ + (n & 127);
                    if (flat == (long)cidx[b]) { cp = g_ckv[b]; kp = g_kr[b]; }
                    else { cp = kvc + flat * KVL; kp = krc + flat * DR; }
                }
                s_ckvp[j] = cp; s_krp[j] = kp; s_vld[j] = valid ? 1 : 0;
            }
            if (tid < NH) { s_m[tid] = -1e30f; s_l[tid] = 0.f; }
            float o0[NH], o1[NH];
            #pragma unroll
            for (int h = 0; h < NH; h++) { o0[h] = 0.f; o1[h] = 0.f; }
            __syncthreads();
            int warp = tid >> 5, lane = tid & 31;
            for (int g = 0; g < SPLITROWS / 8; g++) {
                #pragma unroll
                for (int k = 0; k < 4; k++) {
                    int f = tid + 256 * k;
                    int r = f >> 7, pos = f & 127;
                    ((float4*)&s_kv[r * 512])[pos] = ((const float4*)s_ckvp[g * 8 + r])[pos];
                }
                if (tid < 128) {
                    int r = tid >> 4, pos = tid & 15;
                    ((float4*)&s_kr[r * 64])[pos] = ((const float4*)s_krp[g * 8 + r])[pos];
                }
                __syncthreads();
                {
                    int j = warp;
                    float acc[NH];
                    #pragma unroll
                    for (int h = 0; h < NH; h++) acc[h] = 0.f;
                    #pragma unroll
                    for (int q = 0; q < 4; q++) {
                        float4 v = *(const float4*)&s_kv[j * 512 + 4 * (lane + 32 * q)];
                        #pragma unroll
                        for (int h = 0; h < NH; h++) {
                            float4 ql = *(const float4*)&s_qlat[h * KVL + 4 * (lane + 32 * q)];
                            acc[h] += v.x * ql.x + v.y * ql.y + v.z * ql.z + v.w * ql.w;
                        }
                    }
                    float2 kv2 = *(const float2*)&s_kr[j * 64 + 2 * lane];
                    #pragma unroll
                    for (int h = 0; h < NH; h++) {
                        float2 qp = *(const float2*)&s_qpe[h * DR + 2 * lane];
                        acc[h] += kv2.x * qp.x + kv2.y * qp.y;
                    }
                    #pragma unroll
                    for (int off = 16; off; off >>= 1) {
                        #pragma unroll
                        for (int h = 0; h < NH; h++)
                            acc[h] += __shfl_xor_sync(0xffffffffu, acc[h], off);
                    }
                    if (lane == 0) {
                        bool valid = s_vld[g * 8 + j] != 0;
                        #pragma unroll
                        for (int h = 0; h < NH; h++)
                            s_sc[j * NH + h] = valid ? acc[h] * ATT_SCALE : -1e9f;
                    }
                }
                __syncthreads();
                #pragma unroll
                for (int hh = warp; hh < NH; hh += 8) {
                    float sc = (lane < 8) ? s_sc[lane * NH + hh] : -3.0e38f;
                    float gm = sc;
                    #pragma unroll
                    for (int off = 4; off; off >>= 1) gm = fmaxf(gm, __shfl_xor_sync(0xffffffffu, gm, off));
                    float oldm = s_m[hh];
                    float newm = fmaxf(oldm, gm);
                    float p = (lane < 8) ? __expf(sc - newm) : 0.f;
                    float sl = p;
                    #pragma unroll
                    for (int off = 4; off; off >>= 1) sl += __shfl_xor_sync(0xffffffffu, sl, off);
                    if (lane < 8) s_sc[lane * NH + hh] = p;
                    if (lane == 0) {
                        float fac = __expf(oldm - newm);
                        s_m[hh] = newm;
                        s_l[hh] = s_l[hh] * fac + sl;
                        s_fac[hh] = fac;
                    }
                }
                __syncthreads();
                {
                    float4 f0 = *(const float4*)&s_fac[0];
                    float4 f1 = *(const float4*)&s_fac[4];
                    float4 f2 = *(const float4*)&s_fac[8];
                    float4 f3 = *(const float4*)&s_fac[12];
                    o0[0]  *= f0.x; o0[1]  *= f0.y; o0[2]  *= f0.z; o0[3]  *= f0.w;
                    o0[4]  *= f1.x; o0[5]  *= f1.y; o0[6]  *= f1.z; o0[7]  *= f1.w;
                    o0[8]  *= f2.x; o0[9]  *= f2.y; o0[10] *= f2.z; o0[11] *= f2.w;
                    o0[12] *= f3.x; o0[13] *= f3.y; o0[14] *= f3.z; o0[15] *= f3.w;
                    o1[0]  *= f0.x; o1[1]  *= f0.y; o1[2]  *= f0.z; o1[3]  *= f0.w;
                    o1[4]  *= f1.x; o1[5]  *= f1.y; o1[6]  *= f1.z; o1[7]  *= f1.w;
                    o1[8]  *= f2.x; o1[9]  *= f2.y; o1[10] *= f2.z; o1[11] *= f2.w;
                    o1[12] *= f3.x; o1[13] *= f3.y; o1[14] *= f3.z; o1[15] *= f3.w;
                    int c0 = tid, c1 = tid + 256;
                    #pragma unroll
                    for (int j = 0; j < 8; j++) {
                        float va = s_kv[j * 512 + c0];
                        float vb = s_kv[j * 512 + c1];
                        float4 p0 = *(const float4*)&s_sc[j * NH + 0];
                        float4 p1 = *(const float4*)&s_sc[j * NH + 4];
                        float4 p2 = *(const float4*)&s_sc[j * NH + 8];
                        float4 p3 = *(const float4*)&s_sc[j * NH + 12];
                        o0[0]  += p0.x * va; o0[1]  += p0.y * va; o0[2]  += p0.z * va; o0[3]  += p0.w * va;
                        o0[4]  += p1.x * va; o0[5]  += p1.y * va; o0[6]  += p1.z * va; o0[7]  += p1.w * va;
                        o0[8]  += p2.x * va; o0[9]  += p2.y * va; o0[10] += p2.z * va; o0[11] += p2.w * va;
                        o0[12] += p3.x * va; o0[13] += p3.y * va; o0[14] += p3.z * va; o0[15] += p3.w * va;
                        o1[0]  += p0.x * vb; o1[1]  += p0.y * vb; o1[2]  += p0.z * vb; o1[3]  += p0.w * vb;
                        o1[4]  += p1.x * vb; o1[5]  += p1.y * vb; o1[6]  += p1.z * vb; o1[7]  += p1.w * vb;
                        o1[8]  += p2.x * vb; o1[9]  += p2.y * vb; o1[10] += p2.z * vb; o1[11] += p2.w * vb;
                        o1[12] += p3.x * vb; o1[13] += p3.y * vb; o1[14] += p3.z * vb; o1[15] += p3.w * vb;
                    }
                }
                __syncthreads();
            }
            if (tid < NH) { g_m[b][s][tid] = s_m[tid]; g_l[b][s][tid] = s_l[tid]; }
            {
                int c0 = tid, c1 = tid + 256;
                #pragma unroll
                for (int h = 0; h < NH; h++) {
                    g_op[b][s][h][c0] = o0[h];
                    g_op[b][s][h][c1] = o1[h];
                }
            }
            __syncthreads();
        }
    }
    gsync(6, nb);

    // ===== P6: combine + output projection (float4 reduce) =====
    {
        float* s_olat = (float*)sm_raw;
        float* s_w    = (float*)(sm_raw + 2048);
        float* s_invl = (float*)(sm_raw + 2112);
        for (int u = bx; u < NH * BS; u += nb) {
            int h = u & 15, b = u >> 4;
            if (tid == 0) {
                float M = -1e30f;
                for (int s = 0; s < NSPLIT; s++) M = fmaxf(M, g_m[b][s][h]);
                float L = 0.f;
                for (int s = 0; s < NSPLIT; s++) {
                    float w = __expf(g_m[b][s][h] - M);
                    s_w[s] = w;
                    L += g_l[b][s][h] * w;
                }
                *s_invl = 1.f / L;
            }
            __syncthreads();
            if (tid < 128) {
                int c4 = tid;  // float4 index, 128 x 4 = 512
                float4 a = make_float4(0.f, 0.f, 0.f, 0.f);
                #pragma unroll
                for (int s = 0; s < NSPLIT; s++) {
                    float4 v = ((const float4*)&g_op[b][s][h][0])[c4];
                    float w = s_w[s];
                    a.x += v.x * w; a.y += v.y * w; a.z += v.z * w; a.w += v.w * w;
                }
                float il = *s_invl;
                a.x *= il; a.y *= il; a.z *= il; a.w *= il;
                ((float4*)s_olat)[c4] = a;
            }
            __syncthreads();
            if (tid < DN) {
                int d = tid;
                const float* wk = w_uk + ((size_t)(h * DN + d)) * KVL;
                float a = 0.f;
                #pragma unroll 8
                for (int c = 0; c < KVL; c += 4) {
                    float4 o4 = *(const float4*)&s_olat[c];
                    float4 w4 = *(const float4*)&wk[c];
                    a += o4.x * w4.x + o4.y * w4.y + o4.z * w4.z + o4.w * w4.w;
                }
                out[b * (NH * DN) + h * DN + d] = a;
            }
            __syncthreads();
        }
    }

    // reset sync state for next graph replay
    __syncthreads();
    if (tid == 0) {
        __threadfence();
        unsigned a = atomicAdd(&g_ack, 1u) + 1;
        if (a == (unsigned)nb) {
            #pragma unroll
            for (int i = 0; i < 8; i++) g_barcnt[i] = 0;
            g_ack = 0;
            __threadfence();
        }
    }
}

// ---------------- launch ----------------
extern "C" void kernel_launch(void* const* d_in, const int* in_sizes, int n_in,
                              void* d_out, int out_size) {
    const float* x            = (const float*)d_in[0];
    const float* w_dq         = (const float*)d_in[1];
    const float* w_uq_qr      = (const float*)d_in[2];
    const float* w_uk         = (const float*)d_in[3];
    const float* w_dkv_kr     = (const float*)d_in[4];
    const float* gamma_cq     = (const float*)d_in[5];
    const float* gamma_ckv    = (const float*)d_in[6];
    const float* sinp         = (const float*)d_in[7];
    const float* cosp         = (const float*)d_in[8];
    const int*   cache_index  = (const int*)d_in[9];
    const float* kv_cache     = (const float*)d_in[10];
    const float* kr_cache     = (const float*)d_in[11];
    const int*   block_table  = (const int*)d_in[12];
    const int*   act_seqs     = (const int*)d_in[13];
    const float* w_idx_qb     = (const float*)d_in[14];
    const float* w_idx_k      = (const float*)d_in[15];
    const float* w_idx_proj   = (const float*)d_in[16];
    const float* in_gamma_k   = (const float*)d_in[17];
    const float* in_beta_k    = (const float*)d_in[18];
    const float* index_k_cache= (const float*)d_in[19];
    float* out = (float*)d_out;

    cudaFuncSetAttribute(k_mega, cudaFuncAttributeMaxDynamicSharedMemorySize, SMSZ);

    int sms = 148, bpm = 0;
    cudaDeviceGetAttribute(&sms, cudaDevAttrMultiProcessorCount, 0);
    cudaOccupancyMaxActiveBlocksPerMultiprocessor(&bpm, k_mega, 256, SMSZ);
    if (bpm < 1) bpm = 1;
    int nb = bpm * sms;
    if (nb > NBMAX) nb = NBMAX;

    k_mega<<<nb, 256, SMSZ>>>(x, w_dq, w_uq_qr, w_uk, w_dkv_kr, gamma_cq, gamma_ckv,
                              sinp, cosp, cache_index, kv_cache, kr_cache, block_table,
                              act_seqs, w_idx_qb, w_idx_k, w_idx_proj, in_gamma_k,
                              in_beta_k, index_k_cache, out, nb);
}